// round 1
// baseline (speedup 1.0000x reference)
#include <cuda_runtime.h>

// Problem constants (fixed by the reference: x,y are [8192, 1024] fp32)
#define N_ROWS 8192
#define D      1024
#define WARPS_PER_BLOCK 8
#define NUM_BLOCKS (N_ROWS / WARPS_PER_BLOCK)  // 1024

// Per-block partial sums of -log((cos+1)/2). Every slot is rewritten on every
// call, so no reset pass is needed and the kernel stays deterministic.
__device__ float g_partials[NUM_BLOCKS];

__global__ __launch_bounds__(WARPS_PER_BLOCK * 32)
void row_loss_kernel(const float* __restrict__ x, const float* __restrict__ y) {
    const int warp = threadIdx.x >> 5;
    const int lane = threadIdx.x & 31;
    const int row  = blockIdx.x * WARPS_PER_BLOCK + warp;

    const float4* __restrict__ xr =
        reinterpret_cast<const float4*>(x + (size_t)row * D);
    const float4* __restrict__ yr =
        reinterpret_cast<const float4*>(y + (size_t)row * D);

    float dot = 0.0f, xx = 0.0f, yy = 0.0f;

    // 1024 floats/row = 256 float4. Lane l reads float4 indices l, l+32, ...
    // -> each warp access is a contiguous 512B burst per array. 16 independent
    // 16B loads in flight per thread gives good MLP.
    #pragma unroll
    for (int k = 0; k < 8; k++) {
        float4 a = xr[lane + 32 * k];
        float4 b = yr[lane + 32 * k];
        dot += a.x * b.x + a.y * b.y + a.z * b.z + a.w * b.w;
        xx  += a.x * a.x + a.y * a.y + a.z * a.z + a.w * a.w;
        yy  += b.x * b.x + b.y * b.y + b.z * b.z + b.w * b.w;
    }

    // Warp tree reduction of the three accumulators.
    #pragma unroll
    for (int off = 16; off > 0; off >>= 1) {
        dot += __shfl_down_sync(0xFFFFFFFFu, dot, off);
        xx  += __shfl_down_sync(0xFFFFFFFFu, xx,  off);
        yy  += __shfl_down_sync(0xFFFFFFFFu, yy,  off);
    }

    __shared__ float s_loss[WARPS_PER_BLOCK];
    if (lane == 0) {
        float inv_norm = rsqrtf(fmaxf(xx * yy, 1e-24f));
        float cosv = dot * inv_norm;
        float arg  = fmaxf((cosv + 1.0f) * 0.5f, 1e-30f);
        s_loss[warp] = -logf(arg);
    }
    __syncthreads();

    if (threadIdx.x == 0) {
        float t = 0.0f;
        #pragma unroll
        for (int i = 0; i < WARPS_PER_BLOCK; i++) t += s_loss[i];
        g_partials[blockIdx.x] = t;
    }
}

__global__ __launch_bounds__(NUM_BLOCKS)
void finalize_kernel(float* __restrict__ out) {
    __shared__ float s[NUM_BLOCKS / 32];  // 32 warp partials
    const int tid  = threadIdx.x;         // 0..1023
    const int lane = tid & 31;
    const int warp = tid >> 5;

    float v = g_partials[tid];
    #pragma unroll
    for (int off = 16; off > 0; off >>= 1)
        v += __shfl_down_sync(0xFFFFFFFFu, v, off);
    if (lane == 0) s[warp] = v;
    __syncthreads();

    if (warp == 0) {
        float w = (lane < NUM_BLOCKS / 32) ? s[lane] : 0.0f;
        #pragma unroll
        for (int off = 16; off > 0; off >>= 1)
            w += __shfl_down_sync(0xFFFFFFFFu, w, off);
        if (lane == 0) out[0] = w * (1.0f / (float)N_ROWS);
    }
}

extern "C" void kernel_launch(void* const* d_in, const int* in_sizes, int n_in,
                              void* d_out, int out_size) {
    const float* x = (const float*)d_in[0];
    const float* y = (const float*)d_in[1];
    float* out = (float*)d_out;

    row_loss_kernel<<<NUM_BLOCKS, WARPS_PER_BLOCK * 32>>>(x, y);
    finalize_kernel<<<1, NUM_BLOCKS>>>(out);
}